// round 11
// baseline (speedup 1.0000x reference)
#include <cuda_runtime.h>
#include <cuda_bf16.h>
#include <math.h>

// ---------------- problem constants ----------------
#define CUTOFF        7.0
#define LJ_SIGMA      3.1589
#define LJ_EPSILON    0.1852
#define M_GAMMA       0.73612
#define M_CHARGE      1.1128
#define OH_BOND_EQ    0.9419f
#define OH_BOND_K     1059.162f
#define OH_BOND_ALPHA 2.287f
#define HOH_ANGLE_EQ  1.87448f
#define HOH_ANGLE_K   87.85f
#define P3M_SMEARING  1.4
#define PREFACTOR     332.0637133

#define NMOL_MAX 13824   // 24^3

static constexpr double D_SIG2  = LJ_SIGMA * LJ_SIGMA;
static constexpr double D_SIG6  = D_SIG2 * D_SIG2 * D_SIG2;
static constexpr double D_T     = LJ_SIGMA / CUTOFF;
static constexpr double D_T2    = D_T * D_T;
static constexpr double D_SC6   = D_T2 * D_T2 * D_T2;
static constexpr double D_SHIFT = -4.0 * LJ_EPSILON * D_SC6 * (D_SC6 - 1.0);
static constexpr double D_INVSS = 0.7071067811865475 / P3M_SMEARING;
static constexpr double D_OMF   = (1.0 - M_GAMMA) * 0.5;

#define F_SIG6   ((float)D_SIG6)
#define F_SHIFT  ((float)D_SHIFT)
#define F_INVSS  ((float)D_INVSS)
#define F_OMF    ((float)D_OMF)
#define F_QO     ((float)(-M_CHARGE))
#define F_QH     ((float)(0.5 * M_CHARGE))
#define F_PREF   ((float)PREFACTOR)
#define F_4EPS   ((float)(4.0 * LJ_EPSILON))

#define TB      256
#define BPSM    4
#define NB      (148 * BPSM)  // co-resident (regs<=64, smem 32KB*4=128KB<228KB)
#define UNROLL  4

// Coulomb LUT: f(md) = PREF * erfc(md*INVSS) / md over md in [MD_MIN, MD_MAX]
#define LUT_N    4096
#define MD_MIN   0.25f
#define MD_MAX   7.75f
#define LUT_SCALE ((float)LUT_N / (MD_MAX - MD_MIN))
#define LUT_STEP  ((MD_MAX - MD_MIN) / (float)LUT_N)

// ---------------- device state ----------------
__device__ double   g_energy   = 0.0;
__device__ float4   g_om[NMOL_MAX];
__device__ unsigned g_arrive1  = 0;
__device__ unsigned g_release1 = 0;   // monotonic across graph replays
__device__ unsigned g_arrive2  = 0;

// ---------------- grid barrier (replay-safe, all blocks resident) ----------------
__device__ __forceinline__ void grid_barrier() {
    __syncthreads();
    if (threadIdx.x == 0) {
        volatile unsigned* rel = &g_release1;
        unsigned old = *rel;
        __threadfence();
        unsigned t = atomicAdd(&g_arrive1, 1u);
        if (t == NB - 1) {
            g_arrive1 = 0;
            __threadfence();
            atomicAdd(&g_release1, 1u);
        } else {
            while (*rel == old) { }
        }
        __threadfence();
    }
    __syncthreads();
}

__device__ __forceinline__ float bond_e(float r) {
    float dr  = r - OH_BOND_EQ;
    float adr = dr * OH_BOND_ALPHA;
    return 0.5f * OH_BOND_K * dr * dr * (1.0f - adr + adr * adr * (7.0f / 12.0f));
}

// ---------------- fused kernel ----------------
__global__ __launch_bounds__(TB, BPSM)
void k_fused(const float* __restrict__ dij,
             const int* __restrict__ ni,
             const int* __restrict__ nj,
             int n, int n_mol,
             float* __restrict__ out) {
    __shared__ float2 s_lut[LUT_N];
    __shared__ double s_red[TB / 32];

    const int tid = threadIdx.x;
    const int gtid = blockIdx.x * TB + tid;
    double acc = 0.0;

    // ---- Build Coulomb LUT: entry k = (f(md_k), f(md_{k+1}) - f(md_k)) ----
    for (int k = tid; k < LUT_N; k += TB) {
        float m0 = MD_MIN + (float)k * LUT_STEP;
        float m1 = m0 + LUT_STEP;
        float f0 = F_PREF * erfcf(m0 * F_INVSS) / m0;
        float f1 = F_PREF * erfcf(m1 * F_INVSS) / m1;
        s_lut[k] = make_float2(f0, f1 - f0);
    }

    // ---- Phase 1: per-molecule terms + M-site offsets ----
    // Pair-list order: pair m = (O_m,H1_m) = doh1[m]; pair n_mol+m = (O_m,H2_m) = doh2[m]
    if (gtid < n_mol) {
        int m = gtid;
        const float* p1 = dij + 3 * m;
        const float* p2 = dij + 3 * (n_mol + m);
        float ax = p1[0], ay = p1[1], az = p1[2];
        float bx = p2[0], by = p2[1], bz = p2[2];

        float r1 = sqrtf(ax * ax + ay * ay + az * az);
        float r2 = sqrtf(bx * bx + by * by + bz * bz);
        float eb = bond_e(r1) + bond_e(r2);

        float dotab = ax * bx + ay * by + az * bz;
        float ang = acosf(dotab / (r1 * r2));
        float da = ang - HOH_ANGLE_EQ;
        eb += 0.5f * HOH_ANGLE_K * da * da;

        float ox = F_OMF * (ax + bx);
        float oy = F_OMF * (ay + by);
        float oz = F_OMF * (az + bz);
        g_om[m] = make_float4(ox, oy, oz, 0.0f);

        float m1x = ax - ox, m1y = ay - oy, m1z = az - oz;
        float m2x = bx - ox, m2y = by - oy, m2z = bz - oz;
        float hhx = ax - bx, hhy = ay - by, hhz = az - bz;
        float inv_mh = rsqrtf(m1x * m1x + m1y * m1y + m1z * m1z)
                     + rsqrtf(m2x * m2x + m2y * m2y + m2z * m2z);
        float inv_hh = rsqrtf(hhx * hhx + hhy * hhy + hhz * hhz);
        float eself = (inv_mh * F_QO + inv_hh * F_QH) * F_QH * F_PREF;
        acc = (double)(eb - eself);
    }

    grid_barrier();   // g_om visible; also covers LUT __syncthreads

    // ---- Phase 2: LJ (O-O) + LUT Coulomb over all pairs ----
    const int stride = NB * TB;
    int base = gtid;
    const float4 f4z = make_float4(0.0f, 0.0f, 0.0f, 0.0f);

    for (; base + (UNROLL - 1) * stride < n; base += stride * UNROLL) {
        float dx[UNROLL], dy[UNROLL], dz[UNROLL];
        bool  iO[UNROLL], jO[UNROLL];
        int   mi[UNROLL], mj[UNROLL];

        // A: streaming loads, evict-first
        #pragma unroll
        for (int k = 0; k < UNROLL; k++) {
            int p = base + k * stride;
            int i = __ldcs(ni + p);
            int j = __ldcs(nj + p);
            mi[k] = i / 3;
            mj[k] = j / 3;
            iO[k] = (i == 3 * mi[k]);
            jO[k] = (j == 3 * mj[k]);
        }
        #pragma unroll
        for (int k = 0; k < UNROLL; k++) {
            const float* q = dij + 3 * (base + k * stride);
            dx[k] = __ldcs(q);
            dy[k] = __ldcs(q + 1);
            dz[k] = __ldcs(q + 2);
        }

        // B: batched predicated gathers
        float4 gi[UNROLL], gj[UNROLL];
        #pragma unroll
        for (int k = 0; k < UNROLL; k++) {
            gi[k] = iO[k] ? g_om[mi[k]] : f4z;
            gj[k] = jO[k] ? g_om[mj[k]] : f4z;
        }

        // C: compute (Coulomb via smem LUT)
        float facc = 0.0f;
        #pragma unroll
        for (int k = 0; k < UNROLL; k++) {
            float ox = dx[k] + gj[k].x - gi[k].x;
            float oy = dy[k] + gj[k].y - gi[k].y;
            float oz = dz[k] + gj[k].z - gi[k].z;

            float qq = (iO[k] ? F_QO : F_QH) * (jO[k] ? F_QO : F_QH);

            float md2  = ox * ox + oy * oy + oz * oz;
            float rinv = rsqrtf(md2);
            float md   = md2 * rinv;

            float x = (md - MD_MIN) * LUT_SCALE;
            int   idx = __float2int_rz(x);
            idx = max(0, min(idx, LUT_N - 1));
            float tt = x - (float)idx;
            float2 fe = s_lut[idx];
            facc += qq * fmaf(tt, fe.y, fe.x);

            if (iO[k] && jO[k]) {
                float r2 = dx[k] * dx[k] + dy[k] * dy[k] + dz[k] * dz[k];
                float r6 = r2 * r2 * r2;
                float i6 = __fdividef(F_SIG6, r6);
                facc += F_4EPS * (i6 * i6 - i6) + F_SHIFT;
            }
        }
        acc += (double)facc;
    }

    // remainder (scalar)
    for (int p = base; p < n; p += stride) {
        int i = __ldcs(ni + p);
        int j = __ldcs(nj + p);
        int mi = i / 3, mj = j / 3;
        bool iO = (i == 3 * mi), jO = (j == 3 * mj);
        const float* q = dij + 3 * p;
        float dx = __ldcs(q), dy = __ldcs(q + 1), dz = __ldcs(q + 2);

        float4 gi = iO ? g_om[mi] : f4z;
        float4 gj = jO ? g_om[mj] : f4z;
        float ox = dx + gj.x - gi.x;
        float oy = dy + gj.y - gi.y;
        float oz = dz + gj.z - gi.z;
        float qq = (iO ? F_QO : F_QH) * (jO ? F_QO : F_QH);

        float md2  = ox * ox + oy * oy + oz * oz;
        float rinv = rsqrtf(md2);
        float md   = md2 * rinv;
        float x = (md - MD_MIN) * LUT_SCALE;
        int   idx = __float2int_rz(x);
        idx = max(0, min(idx, LUT_N - 1));
        float tt = x - (float)idx;
        float2 fe = s_lut[idx];
        float facc = qq * fmaf(tt, fe.y, fe.x);

        if (iO && jO) {
            float r2 = dx * dx + dy * dy + dz * dz;
            float r6 = r2 * r2 * r2;
            float i6 = __fdividef(F_SIG6, r6);
            facc += F_4EPS * (i6 * i6 - i6) + F_SHIFT;
        }
        acc += (double)facc;
    }

    // ---- Reduce: block -> global, last block writes result ----
    #pragma unroll
    for (int o = 16; o > 0; o >>= 1)
        acc += __shfl_down_sync(0xffffffffu, acc, o);
    int lane = tid & 31;
    int w    = tid >> 5;
    if (lane == 0) s_red[w] = acc;
    __syncthreads();
    if (w == 0) {
        acc = (lane < TB / 32) ? s_red[lane] : 0.0;
        #pragma unroll
        for (int o = 16; o > 0; o >>= 1)
            acc += __shfl_down_sync(0xffffffffu, acc, o);
        if (lane == 0) {
            atomicAdd(&g_energy, acc);
            __threadfence();
            unsigned t = atomicAdd(&g_arrive2, 1u);
            if (t == NB - 1) {
                g_arrive2 = 0;
                unsigned long long v =
                    atomicExch((unsigned long long*)&g_energy, 0ULL);
                out[0] = (float)__longlong_as_double(v);
            }
        }
    }
}

// ---------------- launch ----------------
extern "C" void kernel_launch(void* const* d_in, const int* in_sizes, int n_in,
                              void* d_out, int out_size) {
    const float* dij = (const float*)d_in[0];
    const int*   ni  = (const int*)d_in[2];
    const int*   nj  = (const int*)d_in[3];
    int n_pairs = in_sizes[2];
    int n_mol   = in_sizes[1] / 3;
    float* out  = (float*)d_out;

    k_fused<<<NB, TB>>>(dij, ni, nj, n_pairs, n_mol, out);
}

// round 12
// speedup vs baseline: 1.4324x; 1.4324x over previous
#include <cuda_runtime.h>
#include <cuda_bf16.h>
#include <math.h>

// ---------------- problem constants ----------------
#define CUTOFF        7.0
#define LJ_SIGMA      3.1589
#define LJ_EPSILON    0.1852
#define M_GAMMA       0.73612
#define M_CHARGE      1.1128
#define OH_BOND_EQ    0.9419f
#define OH_BOND_K     1059.162f
#define OH_BOND_ALPHA 2.287f
#define HOH_ANGLE_EQ  1.87448f
#define HOH_ANGLE_K   87.85f
#define P3M_SMEARING  1.4
#define PREFACTOR     332.0637133

#define NMOL_MAX 13824   // 24^3

static constexpr double D_SIG2  = LJ_SIGMA * LJ_SIGMA;
static constexpr double D_SIG6  = D_SIG2 * D_SIG2 * D_SIG2;
static constexpr double D_T     = LJ_SIGMA / CUTOFF;
static constexpr double D_T2    = D_T * D_T;
static constexpr double D_SC6   = D_T2 * D_T2 * D_T2;
static constexpr double D_SHIFT = -4.0 * LJ_EPSILON * D_SC6 * (D_SC6 - 1.0);
static constexpr double D_INVSS = 0.7071067811865475 / P3M_SMEARING;
static constexpr double D_OMF   = (1.0 - M_GAMMA) * 0.5;

#define F_SIG6   ((float)D_SIG6)
#define F_SHIFT  ((float)D_SHIFT)
#define F_INVSS  ((float)D_INVSS)
#define F_OMF    ((float)D_OMF)
#define F_QO     ((float)(-M_CHARGE))
#define F_QH     ((float)(0.5 * M_CHARGE))
#define F_PREF   ((float)PREFACTOR)
#define F_4EPS   ((float)(4.0 * LJ_EPSILON))

#define TB      256
#define BPSM    4
#define NB      (148 * BPSM)   // co-resident under launch_bounds(256,4)
#define U       2              // pairs per pipeline stage

// ---------------- device state ----------------
__device__ double   g_energy   = 0.0;
__device__ float4   g_om[NMOL_MAX];
__device__ unsigned g_arrive1  = 0;
__device__ unsigned g_release1 = 0;   // monotonic across graph replays
__device__ unsigned g_arrive2  = 0;

// ---------------- grid barrier (replay-safe, all blocks resident) ----------------
__device__ __forceinline__ void grid_barrier() {
    __syncthreads();
    if (threadIdx.x == 0) {
        volatile unsigned* rel = &g_release1;
        unsigned old = *rel;
        __threadfence();
        unsigned t = atomicAdd(&g_arrive1, 1u);
        if (t == NB - 1) {
            g_arrive1 = 0;
            __threadfence();
            atomicAdd(&g_release1, 1u);
        } else {
            while (*rel == old) { }
        }
        __threadfence();
    }
    __syncthreads();
}

__device__ __forceinline__ float bond_e(float r) {
    float dr  = r - OH_BOND_EQ;
    float adr = dr * OH_BOND_ALPHA;
    return 0.5f * OH_BOND_K * dr * dr * (1.0f - adr + adr * adr * (7.0f / 12.0f));
}

// Numerical-Recipes erfcc, relative error ~1e-6 in f32, x >= 0.
__device__ __forceinline__ float fast_erfc(float x) {
    float t = __fdividef(1.0f, fmaf(0.5f, x, 1.0f));
    float p = fmaf(t, 0.17087277f, -0.82215223f);
    p = fmaf(t, p,  1.48851587f);
    p = fmaf(t, p, -1.13520398f);
    p = fmaf(t, p,  0.27886807f);
    p = fmaf(t, p, -0.18628806f);
    p = fmaf(t, p,  0.09678418f);
    p = fmaf(t, p,  0.37409196f);
    p = fmaf(t, p,  1.00002368f);
    p = fmaf(t, p, -1.26551223f);
    return t * __expf(fmaf(-x, x, p));
}

struct Batch {
    int   i[U], j[U];
    float dx[U], dy[U], dz[U];
};

__device__ __forceinline__ void load_batch(Batch& b,
                                           const int* __restrict__ ni,
                                           const int* __restrict__ nj,
                                           const float* __restrict__ dij,
                                           int base, int stride) {
    #pragma unroll
    for (int k = 0; k < U; k++) {
        int p = base + k * stride;
        b.i[k] = __ldcs(ni + p);
        b.j[k] = __ldcs(nj + p);
    }
    #pragma unroll
    for (int k = 0; k < U; k++) {
        const float* q = dij + 3 * (base + k * stride);
        b.dx[k] = __ldcs(q);
        b.dy[k] = __ldcs(q + 1);
        b.dz[k] = __ldcs(q + 2);
    }
}

// scalar pair energy (tail path)
__device__ __forceinline__ float pair_scalar(const int* ni, const int* nj,
                                             const float* dij, int p) {
    int i = ni[p], j = nj[p];
    int mi = i / 3, mj = j / 3;
    bool iO = (i == 3 * mi), jO = (j == 3 * mj);
    const float* q = dij + 3 * p;
    float dx = q[0], dy = q[1], dz = q[2];
    float ox = dx, oy = dy, oz = dz;
    if (jO) { float4 g = g_om[mj]; ox += g.x; oy += g.y; oz += g.z; }
    if (iO) { float4 g = g_om[mi]; ox -= g.x; oy -= g.y; oz -= g.z; }
    float qq   = (iO ? F_QO : F_QH) * (jO ? F_QO : F_QH);
    float md2  = ox * ox + oy * oy + oz * oz;
    float rinv = rsqrtf(md2);
    float md   = md2 * rinv;
    float e    = F_PREF * qq * fast_erfc(md * F_INVSS) * rinv;
    if (iO && jO) {
        float r2 = dx * dx + dy * dy + dz * dz;
        float r6 = r2 * r2 * r2;
        float i6 = __fdividef(F_SIG6, r6);
        e += F_4EPS * (i6 * i6 - i6) + F_SHIFT;
    }
    return e;
}

// ---------------- fused kernel ----------------
__global__ __launch_bounds__(TB, BPSM)
void k_fused(const float* __restrict__ dij,
             const int* __restrict__ ni,
             const int* __restrict__ nj,
             int n, int n_mol,
             float* __restrict__ out) {
    const int tid  = threadIdx.x;
    const int gtid = blockIdx.x * TB + tid;
    double acc = 0.0;

    // ---- Phase 1: per-molecule terms + M-site offsets ----
    // Pair-list order: pair m = (O_m,H1_m) = doh1[m]; pair n_mol+m = (O_m,H2_m) = doh2[m]
    if (gtid < n_mol) {
        int m = gtid;
        const float* p1 = dij + 3 * m;
        const float* p2 = dij + 3 * (n_mol + m);
        float ax = p1[0], ay = p1[1], az = p1[2];
        float bx = p2[0], by = p2[1], bz = p2[2];

        float r1 = sqrtf(ax * ax + ay * ay + az * az);
        float r2 = sqrtf(bx * bx + by * by + bz * bz);
        float eb = bond_e(r1) + bond_e(r2);

        float dotab = ax * bx + ay * by + az * bz;
        float ang = acosf(dotab / (r1 * r2));
        float da = ang - HOH_ANGLE_EQ;
        eb += 0.5f * HOH_ANGLE_K * da * da;

        float ox = F_OMF * (ax + bx);
        float oy = F_OMF * (ay + by);
        float oz = F_OMF * (az + bz);
        g_om[m] = make_float4(ox, oy, oz, 0.0f);

        float m1x = ax - ox, m1y = ay - oy, m1z = az - oz;
        float m2x = bx - ox, m2y = by - oy, m2z = bz - oz;
        float hhx = ax - bx, hhy = ay - by, hhz = az - bz;
        float inv_mh = rsqrtf(m1x * m1x + m1y * m1y + m1z * m1z)
                     + rsqrtf(m2x * m2x + m2y * m2y + m2z * m2z);
        float inv_hh = rsqrtf(hhx * hhx + hhy * hhy + hhz * hhz);
        float eself = (inv_mh * F_QO + inv_hh * F_QH) * F_QH * F_PREF;
        acc = (double)(eb - eself);
    }

    grid_barrier();   // g_om globally visible

    // ---- Phase 2: software-pipelined pair stream ----
    const int stride = NB * TB;
    int base = gtid;
    bool valid = (base + (U - 1) * stride < n);

    Batch cur;
    if (valid) load_batch(cur, ni, nj, dij, base, stride);

    while (valid) {
        int  nbase  = base + U * stride;
        bool nvalid = (nbase + (U - 1) * stride < n);

        // stage 1: gathers for CURRENT (idx regs already resident -> issue now)
        int  mi[U], mj[U];
        bool iO[U], jO[U];
        float ox[U], oy[U], oz[U];
        #pragma unroll
        for (int k = 0; k < U; k++) {
            mi[k] = cur.i[k] / 3;
            mj[k] = cur.j[k] / 3;
            iO[k] = (cur.i[k] == 3 * mi[k]);
            jO[k] = (cur.j[k] == 3 * mj[k]);
            ox[k] = cur.dx[k]; oy[k] = cur.dy[k]; oz[k] = cur.dz[k];
        }
        #pragma unroll
        for (int k = 0; k < U; k++) {
            if (jO[k]) { float4 g = g_om[mj[k]]; ox[k] += g.x; oy[k] += g.y; oz[k] += g.z; }
            if (iO[k]) { float4 g = g_om[mi[k]]; ox[k] -= g.x; oy[k] -= g.y; oz[k] -= g.z; }
        }

        // stage 2: prefetch NEXT batch (latency hides under compute below)
        Batch nxt;
        if (nvalid) load_batch(nxt, ni, nj, dij, nbase, stride);

        // stage 3: compute CURRENT
        float facc = 0.0f;
        #pragma unroll
        for (int k = 0; k < U; k++) {
            float qq   = (iO[k] ? F_QO : F_QH) * (jO[k] ? F_QO : F_QH);
            float md2  = ox[k] * ox[k] + oy[k] * oy[k] + oz[k] * oz[k];
            float rinv = rsqrtf(md2);
            float md   = md2 * rinv;
            facc += F_PREF * qq * fast_erfc(md * F_INVSS) * rinv;

            if (iO[k] && jO[k]) {
                float r2 = cur.dx[k] * cur.dx[k] + cur.dy[k] * cur.dy[k] + cur.dz[k] * cur.dz[k];
                float r6 = r2 * r2 * r2;
                float i6 = __fdividef(F_SIG6, r6);
                facc += F_4EPS * (i6 * i6 - i6) + F_SHIFT;
            }
        }
        acc += (double)facc;

        cur   = nxt;
        base  = nbase;
        valid = nvalid;
    }

    // tail (at most one pair per thread beyond full batches)
    for (int p = base; p < n; p += stride)
        acc += (double)pair_scalar(ni, nj, dij, p);

    // ---- Reduce: block -> global, last block writes result ----
    #pragma unroll
    for (int o = 16; o > 0; o >>= 1)
        acc += __shfl_down_sync(0xffffffffu, acc, o);
    __shared__ double s_red[TB / 32];
    int lane = tid & 31;
    int w    = tid >> 5;
    if (lane == 0) s_red[w] = acc;
    __syncthreads();
    if (w == 0) {
        acc = (lane < TB / 32) ? s_red[lane] : 0.0;
        #pragma unroll
        for (int o = 16; o > 0; o >>= 1)
            acc += __shfl_down_sync(0xffffffffu, acc, o);
        if (lane == 0) {
            atomicAdd(&g_energy, acc);
            __threadfence();
            unsigned t = atomicAdd(&g_arrive2, 1u);
            if (t == NB - 1) {
                g_arrive2 = 0;
                unsigned long long v =
                    atomicExch((unsigned long long*)&g_energy, 0ULL);
                out[0] = (float)__longlong_as_double(v);
            }
        }
    }
}

// ---------------- launch ----------------
extern "C" void kernel_launch(void* const* d_in, const int* in_sizes, int n_in,
                              void* d_out, int out_size) {
    const float* dij = (const float*)d_in[0];
    const int*   ni  = (const int*)d_in[2];
    const int*   nj  = (const int*)d_in[3];
    int n_pairs = in_sizes[2];
    int n_mol   = in_sizes[1] / 3;
    float* out  = (float*)d_out;

    k_fused<<<NB, TB>>>(dij, ni, nj, n_pairs, n_mol, out);
}